// round 11
// baseline (speedup 1.0000x reference)
#include <cuda_runtime.h>
#include <cuda_bf16.h>
#include <cstdint>

#define NN 50000
#define EE 800000
#define DD 128
#define HH 8
#define LRELU_A 0.2f

// ----------------------------- device scratch ------------------------------
__device__ __align__(16) int   SRCS_D[EE];
__device__ __align__(16) int   DSTS_D[EE];
__device__ __align__(16) int   CNT_D[NN];
__device__ __align__(16) int   CUR_D[NN];
__device__ __align__(16) int   ROWPTR_D[NN + 1];
__device__ int                 BSUMS_D[64];
__device__ int                 FLAG_D;            // 0 = int64 edge_index, 1 = int32
__device__ __align__(16) int   SRCP_D[EE];        // CSR-ordered src
__device__ __align__(16) float WP_D[EE];          // CSR-ordered edge weight
__device__ __align__(16) float BS1_D[HH * DD];    // W1[h] @ a1_src[h]
__device__ __align__(16) float BD1_D[HH * DD];
__device__ __align__(16) float ES_D[NN * HH];
__device__ __align__(16) float ED_D[NN * HH];
__device__ __align__(16) float WH_D[NN * DD];     // GAT layer-0 Wh
__device__ __align__(16) float WHC_D[NN * DD];    // GCN h (layer 0, then layer 1)
__device__ __align__(16) float X1A_D[NN * DD];    // GAT layer-0 output (post-ELU)
__device__ __align__(16) float AGG_D[NN * HH * DD]; // [N][h*128+k]
__device__ __align__(16) float X2A_D[NN * DD];
__device__ __align__(16) float X2B_D[NN * DD];

// bf16 hi/lo transposed weights for tensor-core GEMMs: BT[n][k]
__device__ __align__(16) __nv_bfloat16 BT0H_D[DD * DD];
__device__ __align__(16) __nv_bfloat16 BT0L_D[DD * DD];
__device__ __align__(16) __nv_bfloat16 BT1H_D[DD * HH * DD];   // [128][1024]
__device__ __align__(16) __nv_bfloat16 BT1L_D[DD * HH * DD];
__device__ __align__(16) __nv_bfloat16 BG0H_D[DD * DD];
__device__ __align__(16) __nv_bfloat16 BG0L_D[DD * DD];
__device__ __align__(16) __nv_bfloat16 BG1H_D[DD * DD];
__device__ __align__(16) __nv_bfloat16 BG1L_D[DD * DD];

// ----------------------------- helpers -------------------------------------
__device__ __forceinline__ float warp_max(float v) {
#pragma unroll
    for (int o = 16; o > 0; o >>= 1) v = fmaxf(v, __shfl_xor_sync(0xffffffffu, v, o));
    return v;
}
__device__ __forceinline__ float warp_sum(float v) {
#pragma unroll
    for (int o = 16; o > 0; o >>= 1) v += __shfl_xor_sync(0xffffffffu, v, o);
    return v;
}
__device__ __forceinline__ float lrelu(float v) { return v > 0.f ? v : LRELU_A * v; }

__device__ __forceinline__ uint32_t smem_u32(const void* p) {
    uint32_t a;
    asm("{ .reg .u64 t; cvta.to.shared.u64 t, %1; cvt.u32.u64 %0, t; }" : "=r"(a) : "l"(p));
    return a;
}
__device__ __forceinline__ void ldmatrix_x4(uint32_t* r, uint32_t addr) {
    asm volatile("ldmatrix.sync.aligned.m8n8.x4.shared.b16 {%0,%1,%2,%3}, [%4];"
                 : "=r"(r[0]), "=r"(r[1]), "=r"(r[2]), "=r"(r[3]) : "r"(addr));
}
__device__ __forceinline__ void mma_bf16(float* d, const uint32_t* a, const uint32_t* b) {
    asm volatile(
        "mma.sync.aligned.m16n8k16.row.col.f32.bf16.bf16.f32 "
        "{%0,%1,%2,%3}, {%4,%5,%6,%7}, {%8,%9}, {%0,%1,%2,%3};"
        : "+f"(d[0]), "+f"(d[1]), "+f"(d[2]), "+f"(d[3])
        : "r"(a[0]), "r"(a[1]), "r"(a[2]), "r"(a[3]), "r"(b[0]), "r"(b[1]));
}

// ----------------------------- CSR build ------------------------------------
__global__ void zero_kernel() {
    int i = blockIdx.x * blockDim.x + threadIdx.x;
    if (i < NN) { CNT_D[i] = 0; CUR_D[i] = 0; }
    if (i == 0) FLAG_D = 0;
}

__global__ void detect_kernel(const void* __restrict__ ei) {
    int i = blockIdx.x * blockDim.x + threadIdx.x;
    if (i >= EE) return;
    long long v = ((const long long*)ei)[i];
    if (v < 0 || v >= NN) FLAG_D = 1;   // benign race, same value
}

__global__ void convert_kernel(const void* __restrict__ ei) {
    int i = blockIdx.x * blockDim.x + threadIdx.x;
    if (i >= EE) return;
    int s, d;
    if (FLAG_D == 0) {
        s = (int)((const long long*)ei)[i];
        d = (int)((const long long*)ei)[EE + i];
    } else {
        s = ((const int*)ei)[i];
        d = ((const int*)ei)[EE + i];
    }
    SRCS_D[i] = s;
    DSTS_D[i] = d;
    atomicAdd(&CNT_D[d], 1);
}

__global__ void scan1_kernel() {
    __shared__ int sh[1024];
    int b = blockIdx.x, tid = threadIdx.x;
    int i = b * 1024 + tid;
    int v = (i < NN) ? CNT_D[i] : 0;
    sh[tid] = v;
    __syncthreads();
#pragma unroll
    for (int off = 1; off < 1024; off <<= 1) {
        int t = (tid >= off) ? sh[tid - off] : 0;
        __syncthreads();
        sh[tid] += t;
        __syncthreads();
    }
    if (i < NN) ROWPTR_D[i + 1] = sh[tid];
    if (tid == 1023) BSUMS_D[b] = sh[1023];
}

__global__ void scan2_kernel(int nb) {
    if (threadIdx.x == 0) {
        int r = 0;
        for (int b = 0; b < nb; b++) { int t = BSUMS_D[b]; BSUMS_D[b] = r; r += t; }
    }
}

__global__ void scan3_kernel() {
    int i = blockIdx.x * blockDim.x + threadIdx.x;
    if (i < NN) ROWPTR_D[i + 1] += BSUMS_D[i >> 10];
    if (i == 0) ROWPTR_D[0] = 0;
}

__global__ void scatter_kernel(const float* __restrict__ ew) {
    int i = blockIdx.x * blockDim.x + threadIdx.x;
    if (i >= EE) return;
    int d = DSTS_D[i];
    int pos = ROWPTR_D[d] + atomicAdd(&CUR_D[d], 1);
    SRCP_D[pos] = SRCS_D[i];
    WP_D[pos]   = ew[i];
}

// ----------------------------- weight packing (bf16 hi/lo, transposed) ------
__device__ __forceinline__ void split_store(float v, __nv_bfloat16* th, __nv_bfloat16* tl, int idx) {
    __nv_bfloat16 h = __float2bfloat16_rn(v);
    th[idx] = h;
    tl[idx] = __float2bfloat16_rn(v - __bfloat162float(h));
}

// BT0[n][k] = W0[h][k][f] with n = h*16+f
__global__ void packBT0_kernel(const float* __restrict__ W0) {
    int i = blockIdx.x * blockDim.x + threadIdx.x;
    if (i >= DD * DD) return;
    int n = i >> 7, k = i & 127;
    int h = n >> 4, f = n & 15;
    split_store(W0[h * 2048 + k * 16 + f], BT0H_D, BT0L_D, n * 128 + k);
}

// BT1[n][h*128+kk] = W1[h][kk][n]
__global__ void packBT1_kernel(const float* __restrict__ W1) {
    int i = blockIdx.x * blockDim.x + threadIdx.x;
    if (i >= DD * HH * DD) return;
    int n = i >> 10, k = i & 1023;
    int h = k >> 7, kk = k & 127;
    split_store(W1[h * 16384 + kk * 128 + n], BT1H_D, BT1L_D, n * 1024 + k);
}

// BTG[n][k] = G[k][n]
__global__ void packBTG_kernel(const float* __restrict__ G, __nv_bfloat16* th, __nv_bfloat16* tl) {
    int i = blockIdx.x * blockDim.x + threadIdx.x;
    if (i >= DD * DD) return;
    int n = i >> 7, k = i & 127;
    split_store(G[k * 128 + n], th, tl, n * 128 + k);
}

// BS1[h*128+k] = sum_f W1[h][k][f] * a1s[h][f]  (and BD1 with a1d)
__global__ void bvec_kernel(const float* __restrict__ W1,
                            const float* __restrict__ a1s,
                            const float* __restrict__ a1d) {
    int i = blockIdx.x * blockDim.x + threadIdx.x;
    if (i >= HH * DD) return;
    int h = i >> 7;
    const float4* wr  = (const float4*)(W1 + (size_t)i * 128);
    const float4* as4 = (const float4*)(a1s + h * 128);
    const float4* ad4 = (const float4*)(a1d + h * 128);
    float s = 0.f, d = 0.f;
#pragma unroll 8
    for (int j = 0; j < 32; j++) {
        float4 w = wr[j], a = as4[j], b = ad4[j];
        s += w.x * a.x + w.y * a.y + w.z * a.z + w.w * a.w;
        d += w.x * b.x + w.y * b.y + w.z * b.z + w.w * b.w;
    }
    BS1_D[i] = s;
    BD1_D[i] = d;
}

// ----------------------------- tensor-core GEMM (mma.sync, bf16x3) ----------
// C[M,128] = A[M,K](fp32) @ B[K,128] * scale  [optionally fmaxf with maxin row]
// B given as BT hi/lo bf16 [128][K]. D = Ah*Bh + Al*Bh + Ah*Bl, fp32 accumulate.
// CTA tile 64x128, 128 threads (4 warps, 2x2), warp tile 32x64, K chunk 32.
// Static smem single buffer; register prefetch pipelines next chunk's LDGs.
#define GSTR 40

__global__ void __launch_bounds__(128) mma_gemm(const float* __restrict__ A,
                                                const __nv_bfloat16* __restrict__ Bth,
                                                const __nv_bfloat16* __restrict__ Btl,
                                                float* __restrict__ C,
                                                int M, int K, float scale,
                                                const float* __restrict__ maxin) {
    __shared__ __align__(16) __nv_bfloat16 AhS[64 * GSTR];   //  5120 B
    __shared__ __align__(16) __nv_bfloat16 AlS[64 * GSTR];
    __shared__ __align__(16) __nv_bfloat16 BhS[128 * GSTR];  // 10240 B
    __shared__ __align__(16) __nv_bfloat16 BlS[128 * GSTR];

    const int t = threadIdx.x, lane = t & 31, wid = t >> 5;
    const int m0 = blockIdx.x * 64;
    const int wm = (wid & 1) * 32;      // warp m offset
    const int wn = (wid >> 1) * 64;     // warp n offset
    const int nchunk = K >> 5;

    float4 sa[4];
    uint4  sbh[4], sbl[4];

    auto stage = [&](int c) {
        const int k0 = c << 5;
#pragma unroll
        for (int p = 0; p < 4; p++) {
            int idx = p * 128 + t;
            int r = idx >> 3, cc = idx & 7;
            int gr = m0 + r;
            sa[p] = (gr < M) ? *(const float4*)(A + (size_t)gr * K + k0 + cc * 4)
                             : make_float4(0.f, 0.f, 0.f, 0.f);
        }
#pragma unroll
        for (int p = 0; p < 4; p++) {
            int idx = p * 128 + t;
            int r = idx >> 2, q = idx & 3;
            sbh[p] = *(const uint4*)(Bth + (size_t)r * K + k0 + q * 8);
            sbl[p] = *(const uint4*)(Btl + (size_t)r * K + k0 + q * 8);
        }
    };
    auto commit = [&]() {
#pragma unroll
        for (int p = 0; p < 4; p++) {
            int idx = p * 128 + t;
            int r = idx >> 3, cc = idx & 7;
            float4 v = sa[p];
            __nv_bfloat162 h0 = __floats2bfloat162_rn(v.x, v.y);
            __nv_bfloat162 h1 = __floats2bfloat162_rn(v.z, v.w);
            __nv_bfloat162 l0 = __floats2bfloat162_rn(v.x - __bfloat162float(h0.x),
                                                      v.y - __bfloat162float(h0.y));
            __nv_bfloat162 l1 = __floats2bfloat162_rn(v.z - __bfloat162float(h1.x),
                                                      v.w - __bfloat162float(h1.y));
            int e = r * GSTR + cc * 4;
            *(uint32_t*)&AhS[e]     = *(const uint32_t*)&h0;
            *(uint32_t*)&AhS[e + 2] = *(const uint32_t*)&h1;
            *(uint32_t*)&AlS[e]     = *(const uint32_t*)&l0;
            *(uint32_t*)&AlS[e + 2] = *(const uint32_t*)&l1;
        }
#pragma unroll
        for (int p = 0; p < 4; p++) {
            int idx = p * 128 + t;
            int r = idx >> 2, q = idx & 3;
            int e = r * GSTR + q * 8;
            *(uint4*)&BhS[e] = sbh[p];
            *(uint4*)&BlS[e] = sbl[p];
        }
    };

    float acc[2][8][4];
#pragma unroll
    for (int i = 0; i < 2; i++)
#pragma unroll
        for (int j = 0; j < 8; j++)
#pragma unroll
            for (int q = 0; q < 4; q++) acc[i][j][q] = 0.f;

    const uint32_t AhB = smem_u32(AhS), AlB = smem_u32(AlS);
    const uint32_t BhB = smem_u32(BhS), BlB = smem_u32(BlS);
    const int arow = lane & 15, ahalf = lane >> 4;
    const int bn = lane >> 2, bk = (lane & 3) * 2;

    stage(0);
    for (int c = 0; c < nchunk; c++) {
        commit();
        __syncthreads();
        if (c + 1 < nchunk) stage(c + 1);   // next chunk's LDGs overlap compute

#pragma unroll
        for (int ks = 0; ks < 2; ks++) {
            const int kk = ks * 16;
            uint32_t ah[2][4], al[2][4];
#pragma unroll
            for (int mt = 0; mt < 2; mt++) {
                uint32_t off = (uint32_t)((wm + mt * 16 + arow) * GSTR + kk + ahalf * 8) * 2;
                ldmatrix_x4(ah[mt], AhB + off);
                ldmatrix_x4(al[mt], AlB + off);
            }
            uint32_t bh[8][2], bl[8][2];
#pragma unroll
            for (int nt = 0; nt < 8; nt++) {
                uint32_t byt = (uint32_t)((wn + nt * 8 + bn) * GSTR + kk + bk) * 2;
                asm volatile("ld.shared.b32 %0, [%1];" : "=r"(bh[nt][0]) : "r"(BhB + byt));
                asm volatile("ld.shared.b32 %0, [%1];" : "=r"(bh[nt][1]) : "r"(BhB + byt + 16));
                asm volatile("ld.shared.b32 %0, [%1];" : "=r"(bl[nt][0]) : "r"(BlB + byt));
                asm volatile("ld.shared.b32 %0, [%1];" : "=r"(bl[nt][1]) : "r"(BlB + byt + 16));
            }
#pragma unroll
            for (int mt = 0; mt < 2; mt++)
#pragma unroll
                for (int nt = 0; nt < 8; nt++) {
                    mma_bf16(acc[mt][nt], ah[mt], bh[nt]);
                    mma_bf16(acc[mt][nt], al[mt], bh[nt]);
                    mma_bf16(acc[mt][nt], ah[mt], bl[nt]);
                }
        }
        __syncthreads();
    }

    // ---- epilogue (optional fused elementwise max with maxin) ---------------
    const int cg = lane >> 2, ct = (lane & 3) * 2;
#pragma unroll
    for (int mt = 0; mt < 2; mt++) {
#pragma unroll
        for (int nt = 0; nt < 8; nt++) {
            int r0 = m0 + wm + mt * 16 + cg;
            int cc = wn + nt * 8 + ct;
            if (r0 < M) {
                float2 v0 = make_float2(acc[mt][nt][0] * scale, acc[mt][nt][1] * scale);
                if (maxin) {
                    float2 q = *(const float2*)(maxin + (size_t)r0 * 128 + cc);
                    v0.x = fmaxf(v0.x, q.x); v0.y = fmaxf(v0.y, q.y);
                }
                *(float2*)(C + (size_t)r0 * 128 + cc) = v0;
            }
            if (r0 + 8 < M) {
                float2 v1 = make_float2(acc[mt][nt][2] * scale, acc[mt][nt][3] * scale);
                if (maxin) {
                    float2 q = *(const float2*)(maxin + (size_t)(r0 + 8) * 128 + cc);
                    v1.x = fmaxf(v1.x, q.x); v1.y = fmaxf(v1.y, q.y);
                }
                *(float2*)(C + (size_t)(r0 + 8) * 128 + cc) = v1;
            }
        }
    }
}

// ----------------------------- es / ed ---------------------------------------
__global__ void esed0_kernel(const float* __restrict__ a0s,
                             const float* __restrict__ a0d) {
    __shared__ __align__(16) float ss[128];
    __shared__ __align__(16) float sd[128];
    if (threadIdx.x < 128) { ss[threadIdx.x] = a0s[threadIdx.x]; sd[threadIdx.x] = a0d[threadIdx.x]; }
    __syncthreads();
    int i = blockIdx.x * blockDim.x + threadIdx.x;
    if (i >= NN * HH) return;
    int n = i >> 3, h = i & 7;
    const float4* W4 = (const float4*)WH_D;
    const float4* s4 = (const float4*)ss;
    const float4* d4 = (const float4*)sd;
    float es = 0.f, ed = 0.f;
#pragma unroll
    for (int j = 0; j < 4; j++) {
        float4 x = W4[n * 32 + h * 4 + j];
        float4 a = s4[h * 4 + j];
        float4 b = d4[h * 4 + j];
        es += x.x * a.x + x.y * a.y + x.z * a.z + x.w * a.w;
        ed += x.x * b.x + x.y * b.y + x.z * b.z + x.w * b.w;
    }
    ES_D[i] = es;
    ED_D[i] = ed;
}

__global__ void esed1_kernel() {
    __shared__ __align__(16) float bs[1024];
    __shared__ __align__(16) float bd[1024];
    for (int j = threadIdx.x; j < 1024; j += blockDim.x) { bs[j] = BS1_D[j]; bd[j] = BD1_D[j]; }
    __syncthreads();
    int i = blockIdx.x * blockDim.x + threadIdx.x;
    if (i >= NN * HH) return;
    int n = i >> 3, h = i & 7;
    const float4* X4 = (const float4*)X1A_D;
    const float4* b4 = (const float4*)bs;
    const float4* c4 = (const float4*)bd;
    float es = 0.f, ed = 0.f;
#pragma unroll 8
    for (int kk = 0; kk < 32; kk++) {
        float4 x = X4[n * 32 + kk];
        float4 a = b4[h * 32 + kk];
        float4 b = c4[h * 32 + kk];
        es += x.x * a.x + x.y * a.y + x.z * a.z + x.w * a.w;
        ed += x.x * b.x + x.y * b.y + x.z * b.z + x.w * b.w;
    }
    ES_D[i] = es;
    ED_D[i] = ed;
}

// -------------- merged layer 0: GAT(softmax+agg) + GCN agg -------------------
// One warp per node. Pass 1 (strided): per-head attention max + GCN degree sum.
// Pass 2 (serial): two independent 512B row gathers per edge (GAT Wh, GCN h)
// with src/weight prefetched one edge ahead.
__global__ void merged0_kernel() {
    int w = (blockIdx.x * blockDim.x + threadIdx.x) >> 5;
    int lane = threadIdx.x & 31;
    if (w >= NN) return;
    int s0 = ROWPTR_D[w], s1 = ROWPTR_D[w + 1];
    int hidx = lane >> 2;

    float edv[HH];
#pragma unroll
    for (int h = 0; h < HH; h++) edv[h] = ED_D[w * HH + h];

    float m[HH];
#pragma unroll
    for (int h = 0; h < HH; h++) m[h] = -1e30f;
    float dsum = 0.f;
    for (int p = s0 + lane; p < s1; p += 32) {
        int s = SRCP_D[p];
        dsum += WP_D[p];
        float4 e03 = ((const float4*)ES_D)[s * 2];
        float4 e47 = ((const float4*)ES_D)[s * 2 + 1];
        float ev[HH] = {e03.x, e03.y, e03.z, e03.w, e47.x, e47.y, e47.z, e47.w};
#pragma unroll
        for (int h = 0; h < HH; h++) m[h] = fmaxf(m[h], lrelu(ev[h] + edv[h]));
    }
#pragma unroll
    for (int h = 0; h < HH; h++) m[h] = warp_max(m[h]);
    dsum = warp_sum(dsum);
    float dinv = 1.f / fmaxf(dsum, 1e-16f);

    const float mh = m[hidx], edh = edv[hidx];

    const float4* WH4 = (const float4*)WH_D;   // GAT Wh rows
    const float4* HC4 = (const float4*)WHC_D;  // GCN h rows
    float4 ga = make_float4(0.f, 0.f, 0.f, 0.f);
    float4 ca = make_float4(0.f, 0.f, 0.f, 0.f);
    float zsum = 0.f;

    int sN = (s0 < s1) ? SRCP_D[s0] : 0;
    float wN = (s0 < s1) ? WP_D[s0] : 0.f;
    for (int p = s0; p < s1; ++p) {
        int s = sN; float cw = wN;
        if (p + 1 < s1) { sN = SRCP_D[p + 1]; wN = WP_D[p + 1]; }
        float e = ES_D[s * HH + hidx];
        float4 vg = WH4[s * 32 + lane];
        float4 vc = HC4[s * 32 + lane];
        float z = __expf(lrelu(e + edh) - mh);
        ga.x += z * vg.x; ga.y += z * vg.y; ga.z += z * vg.z; ga.w += z * vg.w;
        zsum += z;
        float c = cw * dinv;
        ca.x += c * vc.x; ca.y += c * vc.y; ca.z += c * vc.z; ca.w += c * vc.w;
    }
    float inv = 1.f / fmaxf(zsum, 1e-16f);
    ga.x *= inv; ga.y *= inv; ga.z *= inv; ga.w *= inv;
    ga.x = ga.x > 0.f ? ga.x : __expf(ga.x) - 1.f;
    ga.y = ga.y > 0.f ? ga.y : __expf(ga.y) - 1.f;
    ga.z = ga.z > 0.f ? ga.z : __expf(ga.z) - 1.f;
    ga.w = ga.w > 0.f ? ga.w : __expf(ga.w) - 1.f;
    ((float4*)X1A_D)[w * 32 + lane] = ga;
    ca.x = fmaxf(ca.x, 0.f); ca.y = fmaxf(ca.y, 0.f);
    ca.z = fmaxf(ca.z, 0.f); ca.w = fmaxf(ca.w, 0.f);
    ((float4*)X2A_D)[w * 32 + lane] = ca;
}

// -------------- merged layer 1: GAT(softmax+agg, 8 heads) + GCN agg ----------
__global__ void merged1_kernel() {
    int w = (blockIdx.x * blockDim.x + threadIdx.x) >> 5;
    int lane = threadIdx.x & 31;
    if (w >= NN) return;
    int s0 = ROWPTR_D[w], s1 = ROWPTR_D[w + 1];

    float edv[HH];
#pragma unroll
    for (int h = 0; h < HH; h++) edv[h] = ED_D[w * HH + h];

    float m[HH];
#pragma unroll
    for (int h = 0; h < HH; h++) m[h] = -1e30f;
    float dsum = 0.f;
    for (int p = s0 + lane; p < s1; p += 32) {
        int s = SRCP_D[p];
        dsum += WP_D[p];
        float4 e03 = ((const float4*)ES_D)[s * 2];
        float4 e47 = ((const float4*)ES_D)[s * 2 + 1];
        float ev[HH] = {e03.x, e03.y, e03.z, e03.w, e47.x, e47.y, e47.z, e47.w};
#pragma unroll
        for (int h = 0; h < HH; h++) m[h] = fmaxf(m[h], lrelu(ev[h] + edv[h]));
    }
#pragma unroll
    for (int h = 0; h < HH; h++) m[h] = warp_max(m[h]);
    dsum = warp_sum(dsum);
    float dinv = 1.f / fmaxf(dsum, 1e-16f);

    const float4* X4  = (const float4*)X1A_D;   // GAT values
    const float4* HC4 = (const float4*)WHC_D;   // GCN h rows (layer 1)
    float4 acc[HH];
    float zsum[HH];
#pragma unroll
    for (int h = 0; h < HH; h++) { acc[h] = make_float4(0.f, 0.f, 0.f, 0.f); zsum[h] = 0.f; }
    float4 ca = make_float4(0.f, 0.f, 0.f, 0.f);

    int sN = (s0 < s1) ? SRCP_D[s0] : 0;
    float wN = (s0 < s1) ? WP_D[s0] : 0.f;
    for (int p = s0; p < s1; ++p) {
        int s = sN; float cw = wN;
        if (p + 1 < s1) { sN = SRCP_D[p + 1]; wN = WP_D[p + 1]; }
        float4 e03 = ((const float4*)ES_D)[s * 2];
        float4 e47 = ((const float4*)ES_D)[s * 2 + 1];
        float4 vg = X4[s * 32 + lane];
        float4 vc = HC4[s * 32 + lane];
        float ev[HH] = {e03.x, e03.y, e03.z, e03.w, e47.x, e47.y, e47.z, e47.w};
#pragma unroll
        for (int h = 0; h < HH; h++) {
            float z = __expf(lrelu(ev[h] + edv[h]) - m[h]);
            acc[h].x += z * vg.x;
            acc[h].y += z * vg.y;
            acc[h].z += z * vg.z;
            acc[h].w += z * vg.w;
            zsum[h] += z;
        }
        float c = cw * dinv;
        ca.x += c * vc.x; ca.y += c * vc.y; ca.z += c * vc.z; ca.w += c * vc.w;
    }
    float4* AG4 = (float4*)AGG_D;
    int base = w * 256;
#pragma unroll
    for (int h = 0; h < HH; h++) {
        float inv = 1.f / fmaxf(zsum[h], 1e-16f);
        float4 o = make_float4(acc[h].x * inv, acc[h].y * inv,
                               acc[h].z * inv, acc[h].w * inv);
        AG4[base + h * 32 + lane] = o;
    }
    ca.x = fmaxf(ca.x, 0.f); ca.y = fmaxf(ca.y, 0.f);
    ca.z = fmaxf(ca.z, 0.f); ca.w = fmaxf(ca.w, 0.f);
    ((float4*)X2B_D)[w * 32 + lane] = ca;
}

// ----------------------------- launch ----------------------------------------
extern "C" void kernel_launch(void* const* d_in, const int* in_sizes, int n_in,
                              void* d_out, int out_size) {
    const float* x   = (const float*)d_in[0];
    const void*  ei  = d_in[1];   // int64 or int32 [2, E] — auto-detected
    const float* ew  = (const float*)d_in[2];
    const float* W0  = (const float*)d_in[3];
    const float* a0s = (const float*)d_in[4];
    const float* a0d = (const float*)d_in[5];
    const float* W1  = (const float*)d_in[6];
    const float* a1s = (const float*)d_in[7];
    const float* a1d = (const float*)d_in[8];
    const float* G0  = (const float*)d_in[9];
    const float* G1  = (const float*)d_in[10];
    float* out = (float*)d_out;

    float *wh, *whc, *agg, *x2a, *x2b;
    cudaGetSymbolAddress((void**)&wh,  WH_D);
    cudaGetSymbolAddress((void**)&whc, WHC_D);
    cudaGetSymbolAddress((void**)&agg, AGG_D);
    cudaGetSymbolAddress((void**)&x2a, X2A_D);
    cudaGetSymbolAddress((void**)&x2b, X2B_D);
    __nv_bfloat16 *bt0h, *bt0l, *bt1h, *bt1l, *bg0h, *bg0l, *bg1h, *bg1l;
    cudaGetSymbolAddress((void**)&bt0h, BT0H_D);
    cudaGetSymbolAddress((void**)&bt0l, BT0L_D);
    cudaGetSymbolAddress((void**)&bt1h, BT1H_D);
    cudaGetSymbolAddress((void**)&bt1l, BT1L_D);
    cudaGetSymbolAddress((void**)&bg0h, BG0H_D);
    cudaGetSymbolAddress((void**)&bg0l, BG0L_D);
    cudaGetSymbolAddress((void**)&bg1h, BG1H_D);
    cudaGetSymbolAddress((void**)&bg1l, BG1L_D);

    const int EB   = (EE + 255) / 256;        // 3125
    const int NB   = (NN + 255) / 256;        // 196
    const int NHB  = (NN * HH + 255) / 256;   // 1563
    const int WGB  = (NN * 32 + 255) / 256;   // 6250 (one warp per node)
    const int TCB  = (NN + 63) / 64;          // 782
    const int SCNB = (NN + 1023) / 1024;      // 49

    // CSR build
    zero_kernel<<<NB, 256>>>();
    detect_kernel<<<EB, 256>>>(ei);
    convert_kernel<<<EB, 256>>>(ei);
    scan1_kernel<<<SCNB, 1024>>>();
    scan2_kernel<<<1, 32>>>(SCNB);
    scan3_kernel<<<NB, 256>>>();
    scatter_kernel<<<EB, 256>>>(ew);

    // weight prep (bf16 hi/lo transposed weights + attention bias vectors)
    packBT0_kernel<<<64, 256>>>(W0);
    packBT1_kernel<<<512, 256>>>(W1);
    packBTG_kernel<<<64, 256>>>(G0, bg0h, bg0l);
    packBTG_kernel<<<64, 256>>>(G1, bg1h, bg1l);
    bvec_kernel<<<4, 256>>>(W1, a1s, a1d);

    // layer 0 projections
    mma_gemm<<<TCB, 128>>>(x, bt0h, bt0l, wh,  NN, 128, 1.f, nullptr);
    mma_gemm<<<TCB, 128>>>(x, bg0h, bg0l, whc, NN, 128, 1.f, nullptr);
    esed0_kernel<<<NHB, 256>>>(a0s, a0d);
    merged0_kernel<<<WGB, 256>>>();          // -> X1A (GAT), X2A (GCN)

    // layer 1 projections + merged edge phase
    esed1_kernel<<<NHB, 256>>>();
    mma_gemm<<<TCB, 128>>>(x2a, bg1h, bg1l, whc, NN, 128, 1.f, nullptr);
    merged1_kernel<<<WGB, 256>>>();          // -> AGG (GAT), X2B (GCN)

    // final projection with fused elementwise max(out_gat, X2B)
    mma_gemm<<<TCB, 128>>>(agg, bt1h, bt1l, out, NN, 1024, 0.125f, x2b);
}

// round 12
// speedup vs baseline: 1.0164x; 1.0164x over previous
#include <cuda_runtime.h>
#include <cuda_bf16.h>
#include <cstdint>

#define NN 50000
#define EE 800000
#define DD 128
#define HH 8
#define LRELU_A 0.2f

// ----------------------------- device scratch ------------------------------
__device__ __align__(16) int   SRCS_D[EE];
__device__ __align__(16) int   DSTS_D[EE];
__device__ __align__(16) int   CNT_D[NN];
__device__ __align__(16) int   CUR_D[NN];
__device__ __align__(16) int   ROWPTR_D[NN + 1];
__device__ int                 BSUMS_D[64];
__device__ int                 FLAG_D;            // 0 = int64 edge_index, 1 = int32
__device__ __align__(16) int   SRCP_D[EE];        // CSR-ordered src
__device__ __align__(16) float WP_D[EE];          // CSR-ordered edge weight
__device__ __align__(16) float BS1_D[HH * DD];    // W1[h] @ a1_src[h]
__device__ __align__(16) float BD1_D[HH * DD];
__device__ __align__(16) float ES_D[NN * HH];
__device__ __align__(16) float ED_D[NN * HH];
__device__ __align__(16) float WH_D[NN * DD];     // GAT layer-0 Wh / GCN h
__device__ __align__(16) float X1A_D[NN * DD];    // GAT layer-0 output (post-ELU)
__device__ __align__(16) float AGG_D[NN * HH * DD]; // [N][h*128+k]
__device__ __align__(16) float X2A_D[NN * DD];
__device__ __align__(16) float X2B_D[NN * DD];

// bf16 hi/lo transposed weights for tensor-core GEMMs: BT[n][k]
__device__ __align__(16) __nv_bfloat16 BT0H_D[DD * DD];
__device__ __align__(16) __nv_bfloat16 BT0L_D[DD * DD];
__device__ __align__(16) __nv_bfloat16 BT1H_D[DD * HH * DD];   // [128][1024]
__device__ __align__(16) __nv_bfloat16 BT1L_D[DD * HH * DD];
__device__ __align__(16) __nv_bfloat16 BG0H_D[DD * DD];
__device__ __align__(16) __nv_bfloat16 BG0L_D[DD * DD];
__device__ __align__(16) __nv_bfloat16 BG1H_D[DD * DD];
__device__ __align__(16) __nv_bfloat16 BG1L_D[DD * DD];

// ----------------------------- helpers -------------------------------------
__device__ __forceinline__ float warp_max(float v) {
#pragma unroll
    for (int o = 16; o > 0; o >>= 1) v = fmaxf(v, __shfl_xor_sync(0xffffffffu, v, o));
    return v;
}
__device__ __forceinline__ float warp_sum(float v) {
#pragma unroll
    for (int o = 16; o > 0; o >>= 1) v += __shfl_xor_sync(0xffffffffu, v, o);
    return v;
}
__device__ __forceinline__ float lrelu(float v) { return v > 0.f ? v : LRELU_A * v; }

__device__ __forceinline__ uint32_t smem_u32(const void* p) {
    uint32_t a;
    asm("{ .reg .u64 t; cvta.to.shared.u64 t, %1; cvt.u32.u64 %0, t; }" : "=r"(a) : "l"(p));
    return a;
}
__device__ __forceinline__ void ldmatrix_x4(uint32_t* r, uint32_t addr) {
    asm volatile("ldmatrix.sync.aligned.m8n8.x4.shared.b16 {%0,%1,%2,%3}, [%4];"
                 : "=r"(r[0]), "=r"(r[1]), "=r"(r[2]), "=r"(r[3]) : "r"(addr));
}
__device__ __forceinline__ void mma_bf16(float* d, const uint32_t* a, const uint32_t* b) {
    asm volatile(
        "mma.sync.aligned.m16n8k16.row.col.f32.bf16.bf16.f32 "
        "{%0,%1,%2,%3}, {%4,%5,%6,%7}, {%8,%9}, {%0,%1,%2,%3};"
        : "+f"(d[0]), "+f"(d[1]), "+f"(d[2]), "+f"(d[3])
        : "r"(a[0]), "r"(a[1]), "r"(a[2]), "r"(a[3]), "r"(b[0]), "r"(b[1]));
}

// ----------------------------- CSR build ------------------------------------
__global__ void zero_kernel() {
    int i = blockIdx.x * blockDim.x + threadIdx.x;
    if (i < NN) { CNT_D[i] = 0; CUR_D[i] = 0; }
    if (i == 0) FLAG_D = 0;
}

__global__ void detect_kernel(const void* __restrict__ ei) {
    int i = blockIdx.x * blockDim.x + threadIdx.x;
    if (i >= EE) return;
    long long v = ((const long long*)ei)[i];
    if (v < 0 || v >= NN) FLAG_D = 1;   // benign race, same value
}

__global__ void convert_kernel(const void* __restrict__ ei) {
    int i = blockIdx.x * blockDim.x + threadIdx.x;
    if (i >= EE) return;
    int s, d;
    if (FLAG_D == 0) {
        s = (int)((const long long*)ei)[i];
        d = (int)((const long long*)ei)[EE + i];
    } else {
        s = ((const int*)ei)[i];
        d = ((const int*)ei)[EE + i];
    }
    SRCS_D[i] = s;
    DSTS_D[i] = d;
    atomicAdd(&CNT_D[d], 1);
}

__global__ void scan1_kernel() {
    __shared__ int sh[1024];
    int b = blockIdx.x, tid = threadIdx.x;
    int i = b * 1024 + tid;
    int v = (i < NN) ? CNT_D[i] : 0;
    sh[tid] = v;
    __syncthreads();
#pragma unroll
    for (int off = 1; off < 1024; off <<= 1) {
        int t = (tid >= off) ? sh[tid - off] : 0;
        __syncthreads();
        sh[tid] += t;
        __syncthreads();
    }
    if (i < NN) ROWPTR_D[i + 1] = sh[tid];
    if (tid == 1023) BSUMS_D[b] = sh[1023];
}

__global__ void scan2_kernel(int nb) {
    if (threadIdx.x == 0) {
        int r = 0;
        for (int b = 0; b < nb; b++) { int t = BSUMS_D[b]; BSUMS_D[b] = r; r += t; }
    }
}

__global__ void scan3_kernel() {
    int i = blockIdx.x * blockDim.x + threadIdx.x;
    if (i < NN) ROWPTR_D[i + 1] += BSUMS_D[i >> 10];
    if (i == 0) ROWPTR_D[0] = 0;
}

__global__ void scatter_kernel(const float* __restrict__ ew) {
    int i = blockIdx.x * blockDim.x + threadIdx.x;
    if (i >= EE) return;
    int d = DSTS_D[i];
    int pos = ROWPTR_D[d] + atomicAdd(&CUR_D[d], 1);
    SRCP_D[pos] = SRCS_D[i];
    WP_D[pos]   = ew[i];
}

// ----------------------------- weight packing (bf16 hi/lo, transposed) ------
__device__ __forceinline__ void split_store(float v, __nv_bfloat16* th, __nv_bfloat16* tl, int idx) {
    __nv_bfloat16 h = __float2bfloat16_rn(v);
    th[idx] = h;
    tl[idx] = __float2bfloat16_rn(v - __bfloat162float(h));
}

// BT0[n][k] = W0[h][k][f] with n = h*16+f
__global__ void packBT0_kernel(const float* __restrict__ W0) {
    int i = blockIdx.x * blockDim.x + threadIdx.x;
    if (i >= DD * DD) return;
    int n = i >> 7, k = i & 127;
    int h = n >> 4, f = n & 15;
    split_store(W0[h * 2048 + k * 16 + f], BT0H_D, BT0L_D, n * 128 + k);
}

// BT1[n][h*128+kk] = W1[h][kk][n]
__global__ void packBT1_kernel(const float* __restrict__ W1) {
    int i = blockIdx.x * blockDim.x + threadIdx.x;
    if (i >= DD * HH * DD) return;
    int n = i >> 10, k = i & 1023;
    int h = k >> 7, kk = k & 127;
    split_store(W1[h * 16384 + kk * 128 + n], BT1H_D, BT1L_D, n * 1024 + k);
}

// BTG[n][k] = G[k][n]
__global__ void packBTG_kernel(const float* __restrict__ G, __nv_bfloat16* th, __nv_bfloat16* tl) {
    int i = blockIdx.x * blockDim.x + threadIdx.x;
    if (i >= DD * DD) return;
    int n = i >> 7, k = i & 127;
    split_store(G[k * 128 + n], th, tl, n * 128 + k);
}

// BS1[h*128+k] = sum_f W1[h][k][f] * a1s[h][f]  (and BD1 with a1d)
__global__ void bvec_kernel(const float* __restrict__ W1,
                            const float* __restrict__ a1s,
                            const float* __restrict__ a1d) {
    int i = blockIdx.x * blockDim.x + threadIdx.x;
    if (i >= HH * DD) return;
    int h = i >> 7;
    const float4* wr  = (const float4*)(W1 + (size_t)i * 128);
    const float4* as4 = (const float4*)(a1s + h * 128);
    const float4* ad4 = (const float4*)(a1d + h * 128);
    float s = 0.f, d = 0.f;
#pragma unroll 8
    for (int j = 0; j < 32; j++) {
        float4 w = wr[j], a = as4[j], b = ad4[j];
        s += w.x * a.x + w.y * a.y + w.z * a.z + w.w * a.w;
        d += w.x * b.x + w.y * b.y + w.z * b.z + w.w * b.w;
    }
    BS1_D[i] = s;
    BD1_D[i] = d;
}

// ----------------------------- tensor-core GEMM (mma.sync, bf16x3) ----------
// C[M,128] = A[M,K](fp32) @ B[K,128] * scale  [optionally fmaxf with maxin row]
// B given as BT hi/lo bf16 [128][K]. D = Ah*Bh + Al*Bh + Ah*Bl, fp32 accumulate.
// CTA tile 64x128, 128 threads (4 warps, 2x2), warp tile 32x64, K chunk 32.
// Static smem single buffer; register prefetch pipelines next chunk's LDGs.
#define GSTR 40

__global__ void __launch_bounds__(128) mma_gemm(const float* __restrict__ A,
                                                const __nv_bfloat16* __restrict__ Bth,
                                                const __nv_bfloat16* __restrict__ Btl,
                                                float* __restrict__ C,
                                                int M, int K, float scale,
                                                const float* __restrict__ maxin) {
    __shared__ __align__(16) __nv_bfloat16 AhS[64 * GSTR];   //  5120 B
    __shared__ __align__(16) __nv_bfloat16 AlS[64 * GSTR];
    __shared__ __align__(16) __nv_bfloat16 BhS[128 * GSTR];  // 10240 B
    __shared__ __align__(16) __nv_bfloat16 BlS[128 * GSTR];

    const int t = threadIdx.x, lane = t & 31, wid = t >> 5;
    const int m0 = blockIdx.x * 64;
    const int wm = (wid & 1) * 32;      // warp m offset
    const int wn = (wid >> 1) * 64;     // warp n offset
    const int nchunk = K >> 5;

    float4 sa[4];
    uint4  sbh[4], sbl[4];

    auto stage = [&](int c) {
        const int k0 = c << 5;
#pragma unroll
        for (int p = 0; p < 4; p++) {
            int idx = p * 128 + t;
            int r = idx >> 3, cc = idx & 7;
            int gr = m0 + r;
            sa[p] = (gr < M) ? *(const float4*)(A + (size_t)gr * K + k0 + cc * 4)
                             : make_float4(0.f, 0.f, 0.f, 0.f);
        }
#pragma unroll
        for (int p = 0; p < 4; p++) {
            int idx = p * 128 + t;
            int r = idx >> 2, q = idx & 3;
            sbh[p] = *(const uint4*)(Bth + (size_t)r * K + k0 + q * 8);
            sbl[p] = *(const uint4*)(Btl + (size_t)r * K + k0 + q * 8);
        }
    };
    auto commit = [&]() {
#pragma unroll
        for (int p = 0; p < 4; p++) {
            int idx = p * 128 + t;
            int r = idx >> 3, cc = idx & 7;
            float4 v = sa[p];
            __nv_bfloat162 h0 = __floats2bfloat162_rn(v.x, v.y);
            __nv_bfloat162 h1 = __floats2bfloat162_rn(v.z, v.w);
            __nv_bfloat162 l0 = __floats2bfloat162_rn(v.x - __bfloat162float(h0.x),
                                                      v.y - __bfloat162float(h0.y));
            __nv_bfloat162 l1 = __floats2bfloat162_rn(v.z - __bfloat162float(h1.x),
                                                      v.w - __bfloat162float(h1.y));
            int e = r * GSTR + cc * 4;
            *(uint32_t*)&AhS[e]     = *(const uint32_t*)&h0;
            *(uint32_t*)&AhS[e + 2] = *(const uint32_t*)&h1;
            *(uint32_t*)&AlS[e]     = *(const uint32_t*)&l0;
            *(uint32_t*)&AlS[e + 2] = *(const uint32_t*)&l1;
        }
#pragma unroll
        for (int p = 0; p < 4; p++) {
            int idx = p * 128 + t;
            int r = idx >> 2, q = idx & 3;
            int e = r * GSTR + q * 8;
            *(uint4*)&BhS[e] = sbh[p];
            *(uint4*)&BlS[e] = sbl[p];
        }
    };

    float acc[2][8][4];
#pragma unroll
    for (int i = 0; i < 2; i++)
#pragma unroll
        for (int j = 0; j < 8; j++)
#pragma unroll
            for (int q = 0; q < 4; q++) acc[i][j][q] = 0.f;

    const uint32_t AhB = smem_u32(AhS), AlB = smem_u32(AlS);
    const uint32_t BhB = smem_u32(BhS), BlB = smem_u32(BlS);
    const int arow = lane & 15, ahalf = lane >> 4;
    const int bn = lane >> 2, bk = (lane & 3) * 2;

    stage(0);
    for (int c = 0; c < nchunk; c++) {
        commit();
        __syncthreads();
        if (c + 1 < nchunk) stage(c + 1);   // next chunk's LDGs overlap compute

#pragma unroll
        for (int ks = 0; ks < 2; ks++) {
            const int kk = ks * 16;
            uint32_t ah[2][4], al[2][4];
#pragma unroll
            for (int mt = 0; mt < 2; mt++) {
                uint32_t off = (uint32_t)((wm + mt * 16 + arow) * GSTR + kk + ahalf * 8) * 2;
                ldmatrix_x4(ah[mt], AhB + off);
                ldmatrix_x4(al[mt], AlB + off);
            }
            uint32_t bh[8][2], bl[8][2];
#pragma unroll
            for (int nt = 0; nt < 8; nt++) {
                uint32_t byt = (uint32_t)((wn + nt * 8 + bn) * GSTR + kk + bk) * 2;
                asm volatile("ld.shared.b32 %0, [%1];" : "=r"(bh[nt][0]) : "r"(BhB + byt));
                asm volatile("ld.shared.b32 %0, [%1];" : "=r"(bh[nt][1]) : "r"(BhB + byt + 16));
                asm volatile("ld.shared.b32 %0, [%1];" : "=r"(bl[nt][0]) : "r"(BlB + byt));
                asm volatile("ld.shared.b32 %0, [%1];" : "=r"(bl[nt][1]) : "r"(BlB + byt + 16));
            }
#pragma unroll
            for (int mt = 0; mt < 2; mt++)
#pragma unroll
                for (int nt = 0; nt < 8; nt++) {
                    mma_bf16(acc[mt][nt], ah[mt], bh[nt]);
                    mma_bf16(acc[mt][nt], al[mt], bh[nt]);
                    mma_bf16(acc[mt][nt], ah[mt], bl[nt]);
                }
        }
        __syncthreads();
    }

    // ---- epilogue (optional fused elementwise max with maxin) ---------------
    const int cg = lane >> 2, ct = (lane & 3) * 2;
#pragma unroll
    for (int mt = 0; mt < 2; mt++) {
#pragma unroll
        for (int nt = 0; nt < 8; nt++) {
            int r0 = m0 + wm + mt * 16 + cg;
            int cc = wn + nt * 8 + ct;
            if (r0 < M) {
                float2 v0 = make_float2(acc[mt][nt][0] * scale, acc[mt][nt][1] * scale);
                if (maxin) {
                    float2 q = *(const float2*)(maxin + (size_t)r0 * 128 + cc);
                    v0.x = fmaxf(v0.x, q.x); v0.y = fmaxf(v0.y, q.y);
                }
                *(float2*)(C + (size_t)r0 * 128 + cc) = v0;
            }
            if (r0 + 8 < M) {
                float2 v1 = make_float2(acc[mt][nt][2] * scale, acc[mt][nt][3] * scale);
                if (maxin) {
                    float2 q = *(const float2*)(maxin + (size_t)(r0 + 8) * 128 + cc);
                    v1.x = fmaxf(v1.x, q.x); v1.y = fmaxf(v1.y, q.y);
                }
                *(float2*)(C + (size_t)(r0 + 8) * 128 + cc) = v1;
            }
        }
    }
}

// ----------------------------- es / ed ---------------------------------------
__global__ void esed0_kernel(const float* __restrict__ a0s,
                             const float* __restrict__ a0d) {
    __shared__ __align__(16) float ss[128];
    __shared__ __align__(16) float sd[128];
    if (threadIdx.x < 128) { ss[threadIdx.x] = a0s[threadIdx.x]; sd[threadIdx.x] = a0d[threadIdx.x]; }
    __syncthreads();
    int i = blockIdx.x * blockDim.x + threadIdx.x;
    if (i >= NN * HH) return;
    int n = i >> 3, h = i & 7;
    const float4* W4 = (const float4*)WH_D;
    const float4* s4 = (const float4*)ss;
    const float4* d4 = (const float4*)sd;
    float es = 0.f, ed = 0.f;
#pragma unroll
    for (int j = 0; j < 4; j++) {
        float4 x = W4[n * 32 + h * 4 + j];
        float4 a = s4[h * 4 + j];
        float4 b = d4[h * 4 + j];
        es += x.x * a.x + x.y * a.y + x.z * a.z + x.w * a.w;
        ed += x.x * b.x + x.y * b.y + x.z * b.z + x.w * b.w;
    }
    ES_D[i] = es;
    ED_D[i] = ed;
}

__global__ void esed1_kernel() {
    __shared__ __align__(16) float bs[1024];
    __shared__ __align__(16) float bd[1024];
    for (int j = threadIdx.x; j < 1024; j += blockDim.x) { bs[j] = BS1_D[j]; bd[j] = BD1_D[j]; }
    __syncthreads();
    int i = blockIdx.x * blockDim.x + threadIdx.x;
    if (i >= NN * HH) return;
    int n = i >> 3, h = i & 7;
    const float4* X4 = (const float4*)X1A_D;
    const float4* b4 = (const float4*)bs;
    const float4* c4 = (const float4*)bd;
    float es = 0.f, ed = 0.f;
#pragma unroll 8
    for (int kk = 0; kk < 32; kk++) {
        float4 x = X4[n * 32 + kk];
        float4 a = b4[h * 32 + kk];
        float4 b = c4[h * 32 + kk];
        es += x.x * a.x + x.y * a.y + x.z * a.z + x.w * a.w;
        ed += x.x * b.x + x.y * b.y + x.z * b.z + x.w * b.w;
    }
    ES_D[i] = es;
    ED_D[i] = ed;
}

// -------------------- fused softmax + aggregation, layer 0 -------------------
// One warp per node; src index prefetched one edge ahead in the serial loop.
__global__ void gat0_fused_kernel() {
    int w = (blockIdx.x * blockDim.x + threadIdx.x) >> 5;
    int lane = threadIdx.x & 31;
    if (w >= NN) return;
    int s0 = ROWPTR_D[w], s1 = ROWPTR_D[w + 1];
    int hidx = lane >> 2;

    float edv[HH];
#pragma unroll
    for (int h = 0; h < HH; h++) edv[h] = ED_D[w * HH + h];

    float m[HH];
#pragma unroll
    for (int h = 0; h < HH; h++) m[h] = -1e30f;
    for (int p = s0 + lane; p < s1; p += 32) {
        int s = SRCP_D[p];
        float4 e03 = ((const float4*)ES_D)[s * 2];
        float4 e47 = ((const float4*)ES_D)[s * 2 + 1];
        float ev[HH] = {e03.x, e03.y, e03.z, e03.w, e47.x, e47.y, e47.z, e47.w};
#pragma unroll
        for (int h = 0; h < HH; h++) m[h] = fmaxf(m[h], lrelu(ev[h] + edv[h]));
    }
#pragma unroll
    for (int h = 0; h < HH; h++) m[h] = warp_max(m[h]);

    const float mh = m[hidx], edh = edv[hidx];

    const float4* WH4 = (const float4*)WH_D;
    float4 acc = make_float4(0.f, 0.f, 0.f, 0.f);
    float zsum = 0.f;
    int sN = (s0 < s1) ? SRCP_D[s0] : 0;
    for (int p = s0; p < s1; ++p) {
        int s = sN;
        if (p + 1 < s1) sN = SRCP_D[p + 1];
        float e = ES_D[s * HH + hidx];
        float4 v = WH4[s * 32 + lane];
        float z = __expf(lrelu(e + edh) - mh);
        acc.x += z * v.x; acc.y += z * v.y; acc.z += z * v.z; acc.w += z * v.w;
        zsum += z;
    }
    float inv = 1.f / fmaxf(zsum, 1e-16f);
    acc.x *= inv; acc.y *= inv; acc.z *= inv; acc.w *= inv;
    acc.x = acc.x > 0.f ? acc.x : __expf(acc.x) - 1.f;
    acc.y = acc.y > 0.f ? acc.y : __expf(acc.y) - 1.f;
    acc.z = acc.z > 0.f ? acc.z : __expf(acc.z) - 1.f;
    acc.w = acc.w > 0.f ? acc.w : __expf(acc.w) - 1.f;
    ((float4*)X1A_D)[w * 32 + lane] = acc;
}

// -------------------- fused softmax + aggregation, layer 1 -------------------
__global__ void gat1_fused_kernel() {
    int w = (blockIdx.x * blockDim.x + threadIdx.x) >> 5;
    int lane = threadIdx.x & 31;
    if (w >= NN) return;
    int s0 = ROWPTR_D[w], s1 = ROWPTR_D[w + 1];

    float edv[HH];
#pragma unroll
    for (int h = 0; h < HH; h++) edv[h] = ED_D[w * HH + h];

    float m[HH];
#pragma unroll
    for (int h = 0; h < HH; h++) m[h] = -1e30f;
    for (int p = s0 + lane; p < s1; p += 32) {
        int s = SRCP_D[p];
        float4 e03 = ((const float4*)ES_D)[s * 2];
        float4 e47 = ((const float4*)ES_D)[s * 2 + 1];
        float ev[HH] = {e03.x, e03.y, e03.z, e03.w, e47.x, e47.y, e47.z, e47.w};
#pragma unroll
        for (int h = 0; h < HH; h++) m[h] = fmaxf(m[h], lrelu(ev[h] + edv[h]));
    }
#pragma unroll
    for (int h = 0; h < HH; h++) m[h] = warp_max(m[h]);

    const float4* X4 = (const float4*)X1A_D;
    float4 acc[HH];
    float zsum[HH];
#pragma unroll
    for (int h = 0; h < HH; h++) { acc[h] = make_float4(0.f, 0.f, 0.f, 0.f); zsum[h] = 0.f; }
    int sN = (s0 < s1) ? SRCP_D[s0] : 0;
    for (int p = s0; p < s1; ++p) {
        int s = sN;
        if (p + 1 < s1) sN = SRCP_D[p + 1];
        float4 e03 = ((const float4*)ES_D)[s * 2];
        float4 e47 = ((const float4*)ES_D)[s * 2 + 1];
        float ev[HH] = {e03.x, e03.y, e03.z, e03.w, e47.x, e47.y, e47.z, e47.w};
        float4 v = X4[s * 32 + lane];
#pragma unroll
        for (int h = 0; h < HH; h++) {
            float z = __expf(lrelu(ev[h] + edv[h]) - m[h]);
            acc[h].x += z * v.x;
            acc[h].y += z * v.y;
            acc[h].z += z * v.z;
            acc[h].w += z * v.w;
            zsum[h] += z;
        }
    }
    float4* AG4 = (float4*)AGG_D;
    int base = w * 256;
#pragma unroll
    for (int h = 0; h < HH; h++) {
        float inv = 1.f / fmaxf(zsum[h], 1e-16f);
        float4 o = make_float4(acc[h].x * inv, acc[h].y * inv,
                               acc[h].z * inv, acc[h].w * inv);
        AG4[base + h * 32 + lane] = o;
    }
}

// ----------------------------- GCN aggregation -------------------------------
__global__ void gcn_agg_kernel(const float* __restrict__ Hin, float* __restrict__ Out) {
    int w = (blockIdx.x * blockDim.x + threadIdx.x) >> 5;
    int lane = threadIdx.x & 31;
    if (w >= NN) return;
    int s0 = ROWPTR_D[w], s1 = ROWPTR_D[w + 1];
    float dsum = 0.f;
    for (int p = s0 + lane; p < s1; p += 32) dsum += WP_D[p];
    dsum = warp_sum(dsum);
    float inv = 1.f / fmaxf(dsum, 1e-16f);
    float4 acc = make_float4(0.f, 0.f, 0.f, 0.f);
    const float4* H4 = (const float4*)Hin;
    int sN = (s0 < s1) ? SRCP_D[s0] : 0;
    float wN = (s0 < s1) ? WP_D[s0] : 0.f;
    for (int p = s0; p < s1; ++p) {
        int s = sN; float cw = wN;
        if (p + 1 < s1) { sN = SRCP_D[p + 1]; wN = WP_D[p + 1]; }
        float c = cw * inv;
        float4 v = H4[s * 32 + lane];
        acc.x += c * v.x; acc.y += c * v.y; acc.z += c * v.z; acc.w += c * v.w;
    }
    acc.x = fmaxf(acc.x, 0.f);
    acc.y = fmaxf(acc.y, 0.f);
    acc.z = fmaxf(acc.z, 0.f);
    acc.w = fmaxf(acc.w, 0.f);
    ((float4*)Out)[w * 32 + lane] = acc;
}

// ----------------------------- launch ----------------------------------------
extern "C" void kernel_launch(void* const* d_in, const int* in_sizes, int n_in,
                              void* d_out, int out_size) {
    const float* x   = (const float*)d_in[0];
    const void*  ei  = d_in[1];   // int64 or int32 [2, E] — auto-detected
    const float* ew  = (const float*)d_in[2];
    const float* W0  = (const float*)d_in[3];
    const float* a0s = (const float*)d_in[4];
    const float* a0d = (const float*)d_in[5];
    const float* W1  = (const float*)d_in[6];
    const float* a1s = (const float*)d_in[7];
    const float* a1d = (const float*)d_in[8];
    const float* G0  = (const float*)d_in[9];
    const float* G1  = (const float*)d_in[10];
    float* out = (float*)d_out;

    float *wh, *agg, *x2a, *x2b;
    cudaGetSymbolAddress((void**)&wh,  WH_D);
    cudaGetSymbolAddress((void**)&agg, AGG_D);
    cudaGetSymbolAddress((void**)&x2a, X2A_D);
    cudaGetSymbolAddress((void**)&x2b, X2B_D);
    __nv_bfloat16 *bt0h, *bt0l, *bt1h, *bt1l, *bg0h, *bg0l, *bg1h, *bg1l;
    cudaGetSymbolAddress((void**)&bt0h, BT0H_D);
    cudaGetSymbolAddress((void**)&bt0l, BT0L_D);
    cudaGetSymbolAddress((void**)&bt1h, BT1H_D);
    cudaGetSymbolAddress((void**)&bt1l, BT1L_D);
    cudaGetSymbolAddress((void**)&bg0h, BG0H_D);
    cudaGetSymbolAddress((void**)&bg0l, BG0L_D);
    cudaGetSymbolAddress((void**)&bg1h, BG1H_D);
    cudaGetSymbolAddress((void**)&bg1l, BG1L_D);

    const int EB   = (EE + 255) / 256;        // 3125
    const int NB   = (NN + 255) / 256;        // 196
    const int NHB  = (NN * HH + 255) / 256;   // 1563
    const int WGB  = (NN * 32 + 255) / 256;   // 6250 (one warp per node)
    const int TCB  = (NN + 63) / 64;          // 782
    const int SCNB = (NN + 1023) / 1024;      // 49

    // CSR build
    zero_kernel<<<NB, 256>>>();
    detect_kernel<<<EB, 256>>>(ei);
    convert_kernel<<<EB, 256>>>(ei);
    scan1_kernel<<<SCNB, 1024>>>();
    scan2_kernel<<<1, 32>>>(SCNB);
    scan3_kernel<<<NB, 256>>>();
    scatter_kernel<<<EB, 256>>>(ew);

    // weight prep (bf16 hi/lo transposed weights + attention bias vectors)
    packBT0_kernel<<<64, 256>>>(W0);
    packBT1_kernel<<<512, 256>>>(W1);
    packBTG_kernel<<<64, 256>>>(G0, bg0h, bg0l);
    packBTG_kernel<<<64, 256>>>(G1, bg1h, bg1l);
    bvec_kernel<<<4, 256>>>(W1, a1s, a1d);

    // GAT layer 0
    mma_gemm<<<TCB, 128>>>(x, bt0h, bt0l, wh, NN, 128, 1.f, nullptr);
    esed0_kernel<<<NHB, 256>>>(a0s, a0d);
    gat0_fused_kernel<<<WGB, 256>>>();

    // GAT layer 1
    esed1_kernel<<<NHB, 256>>>();
    gat1_fused_kernel<<<WGB, 256>>>();

    // GCN branch
    mma_gemm<<<TCB, 128>>>(x, bg0h, bg0l, wh, NN, 128, 1.f, nullptr);
    gcn_agg_kernel<<<WGB, 256>>>(wh, x2a);
    mma_gemm<<<TCB, 128>>>(x2a, bg1h, bg1l, wh, NN, 128, 1.f, nullptr);
    gcn_agg_kernel<<<WGB, 256>>>(wh, x2b);

    // final GAT projection with fused elementwise max(out_gat, X2B)
    mma_gemm<<<TCB, 128>>>(agg, bt1h, bt1l, out, NN, 1024, 0.125f, x2b);
}

// round 14
// speedup vs baseline: 1.0839x; 1.0664x over previous
#include <cuda_runtime.h>
#include <cuda_bf16.h>
#include <cstdint>

#define NN 50000
#define EE 800000
#define DD 128
#define HH 8
#define LRELU_A 0.2f

// ----------------------------- device scratch ------------------------------
__device__ __align__(16) int   SRCS_D[EE];
__device__ __align__(16) int   DSTS_D[EE];
__device__ __align__(16) int   CNT_D[NN];
__device__ __align__(16) int   CUR_D[NN];
__device__ __align__(16) int   ROWPTR_D[NN + 1];
__device__ int                 BSUMS_D[64];
__device__ int                 FLAG_D;            // 0 = int64 edge_index, 1 = int32
__device__ __align__(16) int   SRCP_D[EE];        // CSR-ordered src
__device__ __align__(16) float WP_D[EE];          // CSR-ordered edge weight
__device__ __align__(16) float BS1_D[HH * DD];    // W1[h] @ a1_src[h]
__device__ __align__(16) float BD1_D[HH * DD];
__device__ __align__(16) float ES_D[NN * HH];
__device__ __align__(16) float ED_D[NN * HH];
__device__ __align__(16) float WH_D[NN * DD];     // GAT layer-0 Wh / GCN h
__device__ __align__(16) float X1A_D[NN * DD];    // GAT layer-0 output (post-ELU)
__device__ __align__(16) float AGG_D[NN * HH * DD]; // [N][h*128+k]
__device__ __align__(16) float X2A_D[NN * DD];
__device__ __align__(16) float X2B_D[NN * DD];

// bf16 hi/lo transposed weights for tensor-core GEMMs: BT[n][k]
__device__ __align__(16) __nv_bfloat16 BT0H_D[DD * DD];
__device__ __align__(16) __nv_bfloat16 BT0L_D[DD * DD];
__device__ __align__(16) __nv_bfloat16 BT1H_D[DD * HH * DD];   // [128][1024]
__device__ __align__(16) __nv_bfloat16 BT1L_D[DD * HH * DD];
__device__ __align__(16) __nv_bfloat16 BG0H_D[DD * DD];
__device__ __align__(16) __nv_bfloat16 BG0L_D[DD * DD];
__device__ __align__(16) __nv_bfloat16 BG1H_D[DD * DD];
__device__ __align__(16) __nv_bfloat16 BG1L_D[DD * DD];

// ----------------------------- helpers -------------------------------------
__device__ __forceinline__ float warp_max(float v) {
#pragma unroll
    for (int o = 16; o > 0; o >>= 1) v = fmaxf(v, __shfl_xor_sync(0xffffffffu, v, o));
    return v;
}
__device__ __forceinline__ float warp_sum(float v) {
#pragma unroll
    for (int o = 16; o > 0; o >>= 1) v += __shfl_xor_sync(0xffffffffu, v, o);
    return v;
}
__device__ __forceinline__ float lrelu(float v) { return v > 0.f ? v : LRELU_A * v; }

__device__ __forceinline__ uint32_t smem_u32(const void* p) {
    uint32_t a;
    asm("{ .reg .u64 t; cvta.to.shared.u64 t, %1; cvt.u32.u64 %0, t; }" : "=r"(a) : "l"(p));
    return a;
}
__device__ __forceinline__ void ldmatrix_x4(uint32_t* r, uint32_t addr) {
    asm volatile("ldmatrix.sync.aligned.m8n8.x4.shared.b16 {%0,%1,%2,%3}, [%4];"
                 : "=r"(r[0]), "=r"(r[1]), "=r"(r[2]), "=r"(r[3]) : "r"(addr));
}
__device__ __forceinline__ void mma_bf16(float* d, const uint32_t* a, const uint32_t* b) {
    asm volatile(
        "mma.sync.aligned.m16n8k16.row.col.f32.bf16.bf16.f32 "
        "{%0,%1,%2,%3}, {%4,%5,%6,%7}, {%8,%9}, {%0,%1,%2,%3};"
        : "+f"(d[0]), "+f"(d[1]), "+f"(d[2]), "+f"(d[3])
        : "r"(a[0]), "r"(a[1]), "r"(a[2]), "r"(a[3]), "r"(b[0]), "r"(b[1]));
}

// ----------------------------- CSR build ------------------------------------
__global__ void zero_kernel() {
    int i = blockIdx.x * blockDim.x + threadIdx.x;
    if (i < NN) { CNT_D[i] = 0; CUR_D[i] = 0; }
    if (i == 0) FLAG_D = 0;
}

__global__ void detect_kernel(const void* __restrict__ ei) {
    int i = blockIdx.x * blockDim.x + threadIdx.x;
    if (i >= EE) return;
    long long v = ((const long long*)ei)[i];
    if (v < 0 || v >= NN) FLAG_D = 1;   // benign race, same value
}

__global__ void convert_kernel(const void* __restrict__ ei) {
    int i = blockIdx.x * blockDim.x + threadIdx.x;
    if (i >= EE) return;
    int s, d;
    if (FLAG_D == 0) {
        s = (int)((const long long*)ei)[i];
        d = (int)((const long long*)ei)[EE + i];
    } else {
        s = ((const int*)ei)[i];
        d = ((const int*)ei)[EE + i];
    }
    SRCS_D[i] = s;
    DSTS_D[i] = d;
    atomicAdd(&CNT_D[d], 1);
}

__global__ void scan1_kernel() {
    __shared__ int sh[1024];
    int b = blockIdx.x, tid = threadIdx.x;
    int i = b * 1024 + tid;
    int v = (i < NN) ? CNT_D[i] : 0;
    sh[tid] = v;
    __syncthreads();
#pragma unroll
    for (int off = 1; off < 1024; off <<= 1) {
        int t = (tid >= off) ? sh[tid - off] : 0;
        __syncthreads();
        sh[tid] += t;
        __syncthreads();
    }
    if (i < NN) ROWPTR_D[i + 1] = sh[tid];
    if (tid == 1023) BSUMS_D[b] = sh[1023];
}

__global__ void scan2_kernel(int nb) {
    if (threadIdx.x == 0) {
        int r = 0;
        for (int b = 0; b < nb; b++) { int t = BSUMS_D[b]; BSUMS_D[b] = r; r += t; }
    }
}

__global__ void scan3_kernel() {
    int i = blockIdx.x * blockDim.x + threadIdx.x;
    if (i < NN) ROWPTR_D[i + 1] += BSUMS_D[i >> 10];
    if (i == 0) ROWPTR_D[0] = 0;
}

__global__ void scatter_kernel(const float* __restrict__ ew) {
    int i = blockIdx.x * blockDim.x + threadIdx.x;
    if (i >= EE) return;
    int d = DSTS_D[i];
    int pos = ROWPTR_D[d] + atomicAdd(&CUR_D[d], 1);
    SRCP_D[pos] = SRCS_D[i];
    WP_D[pos]   = ew[i];
}

// ----------------------------- weight packing (bf16 hi/lo, transposed) ------
__device__ __forceinline__ void split_store(float v, __nv_bfloat16* th, __nv_bfloat16* tl, int idx) {
    __nv_bfloat16 h = __float2bfloat16_rn(v);
    th[idx] = h;
    tl[idx] = __float2bfloat16_rn(v - __bfloat162float(h));
}

// BT0[n][k] = W0[h][k][f] with n = h*16+f
__global__ void packBT0_kernel(const float* __restrict__ W0) {
    int i = blockIdx.x * blockDim.x + threadIdx.x;
    if (i >= DD * DD) return;
    int n = i >> 7, k = i & 127;
    int h = n >> 4, f = n & 15;
    split_store(W0[h * 2048 + k * 16 + f], BT0H_D, BT0L_D, n * 128 + k);
}

// BT1[n][h*128+kk] = W1[h][kk][n]
__global__ void packBT1_kernel(const float* __restrict__ W1) {
    int i = blockIdx.x * blockDim.x + threadIdx.x;
    if (i >= DD * HH * DD) return;
    int n = i >> 10, k = i & 1023;
    int h = k >> 7, kk = k & 127;
    split_store(W1[h * 16384 + kk * 128 + n], BT1H_D, BT1L_D, n * 1024 + k);
}

// BTG[n][k] = G[k][n]
__global__ void packBTG_kernel(const float* __restrict__ G, __nv_bfloat16* th, __nv_bfloat16* tl) {
    int i = blockIdx.x * blockDim.x + threadIdx.x;
    if (i >= DD * DD) return;
    int n = i >> 7, k = i & 127;
    split_store(G[k * 128 + n], th, tl, n * 128 + k);
}

// BS1[h*128+k] = sum_f W1[h][k][f] * a1s[h][f]  (and BD1 with a1d)
__global__ void bvec_kernel(const float* __restrict__ W1,
                            const float* __restrict__ a1s,
                            const float* __restrict__ a1d) {
    int i = blockIdx.x * blockDim.x + threadIdx.x;
    if (i >= HH * DD) return;
    int h = i >> 7;
    const float4* wr  = (const float4*)(W1 + (size_t)i * 128);
    const float4* as4 = (const float4*)(a1s + h * 128);
    const float4* ad4 = (const float4*)(a1d + h * 128);
    float s = 0.f, d = 0.f;
#pragma unroll 8
    for (int j = 0; j < 32; j++) {
        float4 w = wr[j], a = as4[j], b = ad4[j];
        s += w.x * a.x + w.y * a.y + w.z * a.z + w.w * a.w;
        d += w.x * b.x + w.y * b.y + w.z * b.z + w.w * b.w;
    }
    BS1_D[i] = s;
    BD1_D[i] = d;
}

// ----------------------------- tensor-core GEMM (mma.sync, bf16x3) ----------
// C[M,128] = A[M,K](fp32) @ B[K,128] * scale  [optionally fmaxf with maxin row]
// B given as BT hi/lo bf16 [128][K]. D = Ah*Bh + Al*Bh + Ah*Bl, fp32 accumulate.
// CTA tile 64x128, 128 threads (4 warps, 2x2), warp tile 32x64, K chunk 32.
// Static smem single buffer; register prefetch pipelines next chunk's LDGs.
#define GSTR 40

__global__ void __launch_bounds__(128) mma_gemm(const float* __restrict__ A,
                                                const __nv_bfloat16* __restrict__ Bth,
                                                const __nv_bfloat16* __restrict__ Btl,
                                                float* __restrict__ C,
                                                int M, int K, float scale,
                                                const float* __restrict__ maxin) {
    __shared__ __align__(16) __nv_bfloat16 AhS[64 * GSTR];   //  5120 B
    __shared__ __align__(16) __nv_bfloat16 AlS[64 * GSTR];
    __shared__ __align__(16) __nv_bfloat16 BhS[128 * GSTR];  // 10240 B
    __shared__ __align__(16) __nv_bfloat16 BlS[128 * GSTR];

    const int t = threadIdx.x, lane = t & 31, wid = t >> 5;
    const int m0 = blockIdx.x * 64;
    const int wm = (wid & 1) * 32;      // warp m offset
    const int wn = (wid >> 1) * 64;     // warp n offset
    const int nchunk = K >> 5;

    float4 sa[4];
    uint4  sbh[4], sbl[4];

    auto stage = [&](int c) {
        const int k0 = c << 5;
#pragma unroll
        for (int p = 0; p < 4; p++) {
            int idx = p * 128 + t;
            int r = idx >> 3, cc = idx & 7;
            int gr = m0 + r;
            sa[p] = (gr < M) ? *(const float4*)(A + (size_t)gr * K + k0 + cc * 4)
                             : make_float4(0.f, 0.f, 0.f, 0.f);
        }
#pragma unroll
        for (int p = 0; p < 4; p++) {
            int idx = p * 128 + t;
            int r = idx >> 2, q = idx & 3;
            sbh[p] = *(const uint4*)(Bth + (size_t)r * K + k0 + q * 8);
            sbl[p] = *(const uint4*)(Btl + (size_t)r * K + k0 + q * 8);
        }
    };
    auto commit = [&]() {
#pragma unroll
        for (int p = 0; p < 4; p++) {
            int idx = p * 128 + t;
            int r = idx >> 3, cc = idx & 7;
            float4 v = sa[p];
            __nv_bfloat162 h0 = __floats2bfloat162_rn(v.x, v.y);
            __nv_bfloat162 h1 = __floats2bfloat162_rn(v.z, v.w);
            __nv_bfloat162 l0 = __floats2bfloat162_rn(v.x - __bfloat162float(h0.x),
                                                      v.y - __bfloat162float(h0.y));
            __nv_bfloat162 l1 = __floats2bfloat162_rn(v.z - __bfloat162float(h1.x),
                                                      v.w - __bfloat162float(h1.y));
            int e = r * GSTR + cc * 4;
            *(uint32_t*)&AhS[e]     = *(const uint32_t*)&h0;
            *(uint32_t*)&AhS[e + 2] = *(const uint32_t*)&h1;
            *(uint32_t*)&AlS[e]     = *(const uint32_t*)&l0;
            *(uint32_t*)&AlS[e + 2] = *(const uint32_t*)&l1;
        }
#pragma unroll
        for (int p = 0; p < 4; p++) {
            int idx = p * 128 + t;
            int r = idx >> 2, q = idx & 3;
            int e = r * GSTR + q * 8;
            *(uint4*)&BhS[e] = sbh[p];
            *(uint4*)&BlS[e] = sbl[p];
        }
    };

    float acc[2][8][4];
#pragma unroll
    for (int i = 0; i < 2; i++)
#pragma unroll
        for (int j = 0; j < 8; j++)
#pragma unroll
            for (int q = 0; q < 4; q++) acc[i][j][q] = 0.f;

    const uint32_t AhB = smem_u32(AhS), AlB = smem_u32(AlS);
    const uint32_t BhB = smem_u32(BhS), BlB = smem_u32(BlS);
    const int arow = lane & 15, ahalf = lane >> 4;
    const int bn = lane >> 2, bk = (lane & 3) * 2;

    stage(0);
    for (int c = 0; c < nchunk; c++) {
        commit();
        __syncthreads();
        if (c + 1 < nchunk) stage(c + 1);   // next chunk's LDGs overlap compute

#pragma unroll
        for (int ks = 0; ks < 2; ks++) {
            const int kk = ks * 16;
            uint32_t ah[2][4], al[2][4];
#pragma unroll
            for (int mt = 0; mt < 2; mt++) {
                uint32_t off = (uint32_t)((wm + mt * 16 + arow) * GSTR + kk + ahalf * 8) * 2;
                ldmatrix_x4(ah[mt], AhB + off);
                ldmatrix_x4(al[mt], AlB + off);
            }
            uint32_t bh[8][2], bl[8][2];
#pragma unroll
            for (int nt = 0; nt < 8; nt++) {
                uint32_t byt = (uint32_t)((wn + nt * 8 + bn) * GSTR + kk + bk) * 2;
                asm volatile("ld.shared.b32 %0, [%1];" : "=r"(bh[nt][0]) : "r"(BhB + byt));
                asm volatile("ld.shared.b32 %0, [%1];" : "=r"(bh[nt][1]) : "r"(BhB + byt + 16));
                asm volatile("ld.shared.b32 %0, [%1];" : "=r"(bl[nt][0]) : "r"(BlB + byt));
                asm volatile("ld.shared.b32 %0, [%1];" : "=r"(bl[nt][1]) : "r"(BlB + byt + 16));
            }
#pragma unroll
            for (int mt = 0; mt < 2; mt++)
#pragma unroll
                for (int nt = 0; nt < 8; nt++) {
                    mma_bf16(acc[mt][nt], ah[mt], bh[nt]);
                    mma_bf16(acc[mt][nt], al[mt], bh[nt]);
                    mma_bf16(acc[mt][nt], ah[mt], bl[nt]);
                }
        }
        __syncthreads();
    }

    // ---- epilogue (optional fused elementwise max with maxin) ---------------
    const int cg = lane >> 2, ct = (lane & 3) * 2;
#pragma unroll
    for (int mt = 0; mt < 2; mt++) {
#pragma unroll
        for (int nt = 0; nt < 8; nt++) {
            int r0 = m0 + wm + mt * 16 + cg;
            int cc = wn + nt * 8 + ct;
            if (r0 < M) {
                float2 v0 = make_float2(acc[mt][nt][0] * scale, acc[mt][nt][1] * scale);
                if (maxin) {
                    float2 q = *(const float2*)(maxin + (size_t)r0 * 128 + cc);
                    v0.x = fmaxf(v0.x, q.x); v0.y = fmaxf(v0.y, q.y);
                }
                *(float2*)(C + (size_t)r0 * 128 + cc) = v0;
            }
            if (r0 + 8 < M) {
                float2 v1 = make_float2(acc[mt][nt][2] * scale, acc[mt][nt][3] * scale);
                if (maxin) {
                    float2 q = *(const float2*)(maxin + (size_t)(r0 + 8) * 128 + cc);
                    v1.x = fmaxf(v1.x, q.x); v1.y = fmaxf(v1.y, q.y);
                }
                *(float2*)(C + (size_t)(r0 + 8) * 128 + cc) = v1;
            }
        }
    }
}

// ----------------------------- es / ed ---------------------------------------
__global__ void esed0_kernel(const float* __restrict__ a0s,
                             const float* __restrict__ a0d) {
    __shared__ __align__(16) float ss[128];
    __shared__ __align__(16) float sd[128];
    if (threadIdx.x < 128) { ss[threadIdx.x] = a0s[threadIdx.x]; sd[threadIdx.x] = a0d[threadIdx.x]; }
    __syncthreads();
    int i = blockIdx.x * blockDim.x + threadIdx.x;
    if (i >= NN * HH) return;
    int n = i >> 3, h = i & 7;
    const float4* W4 = (const float4*)WH_D;
    const float4* s4 = (const float4*)ss;
    const float4* d4 = (const float4*)sd;
    float es = 0.f, ed = 0.f;
#pragma unroll
    for (int j = 0; j < 4; j++) {
        float4 x = W4[n * 32 + h * 4 + j];
        float4 a = s4[h * 4 + j];
        float4 b = d4[h * 4 + j];
        es += x.x * a.x + x.y * a.y + x.z * a.z + x.w * a.w;
        ed += x.x * b.x + x.y * b.y + x.z * b.z + x.w * b.w;
    }
    ES_D[i] = es;
    ED_D[i] = ed;
}

__global__ void esed1_kernel() {
    __shared__ __align__(16) float bs[1024];
    __shared__ __align__(16) float bd[1024];
    for (int j = threadIdx.x; j < 1024; j += blockDim.x) { bs[j] = BS1_D[j]; bd[j] = BD1_D[j]; }
    __syncthreads();
    int i = blockIdx.x * blockDim.x + threadIdx.x;
    if (i >= NN * HH) return;
    int n = i >> 3, h = i & 7;
    const float4* X4 = (const float4*)X1A_D;
    const float4* b4 = (const float4*)bs;
    const float4* c4 = (const float4*)bd;
    float es = 0.f, ed = 0.f;
#pragma unroll 8
    for (int kk = 0; kk < 32; kk++) {
        float4 x = X4[n * 32 + kk];
        float4 a = b4[h * 32 + kk];
        float4 b = c4[h * 32 + kk];
        es += x.x * a.x + x.y * a.y + x.z * a.z + x.w * a.w;
        ed += x.x * b.x + x.y * b.y + x.z * b.z + x.w * b.w;
    }
    ES_D[i] = es;
    ED_D[i] = ed;
}

// -------------------- fused softmax + aggregation, layer 0 -------------------
// One warp per node (exact R8 form — no manual prefetch; ptxas batches LDGs).
__global__ void gat0_fused_kernel() {
    int w = (blockIdx.x * blockDim.x + threadIdx.x) >> 5;
    int lane = threadIdx.x & 31;
    if (w >= NN) return;
    int s0 = ROWPTR_D[w], s1 = ROWPTR_D[w + 1];
    int hidx = lane >> 2;

    float edv[HH];
#pragma unroll
    for (int h = 0; h < HH; h++) edv[h] = ED_D[w * HH + h];

    float m[HH];
#pragma unroll
    for (int h = 0; h < HH; h++) m[h] = -1e30f;
    for (int p = s0 + lane; p < s1; p += 32) {
        int s = SRCP_D[p];
        float4 e03 = ((const float4*)ES_D)[s * 2];
        float4 e47 = ((const float4*)ES_D)[s * 2 + 1];
        float ev[HH] = {e03.x, e03.y, e03.z, e03.w, e47.x, e47.y, e47.z, e47.w};
#pragma unroll
        for (int h = 0; h < HH; h++) m[h] = fmaxf(m[h], lrelu(ev[h] + edv[h]));
    }
#pragma unroll
    for (int h = 0; h < HH; h++) m[h] = warp_max(m[h]);

    const float mh = m[hidx], edh = edv[hidx];

    const float4* WH4 = (const float4*)WH_D;
    float4 acc = make_float4(0.f, 0.f, 0.f, 0.f);
    float zsum = 0.f;
    for (int p = s0; p < s1; ++p) {
        int s = SRCP_D[p];
        float e = ES_D[s * HH + hidx];
        float z = __expf(lrelu(e + edh) - mh);
        float4 v = WH4[s * 32 + lane];
        acc.x += z * v.x; acc.y += z * v.y; acc.z += z * v.z; acc.w += z * v.w;
        zsum += z;
    }
    float inv = 1.f / fmaxf(zsum, 1e-16f);
    acc.x *= inv; acc.y *= inv; acc.z *= inv; acc.w *= inv;
    acc.x = acc.x > 0.f ? acc.x : __expf(acc.x) - 1.f;
    acc.y = acc.y > 0.f ? acc.y : __expf(acc.y) - 1.f;
    acc.z = acc.z > 0.f ? acc.z : __expf(acc.z) - 1.f;
    acc.w = acc.w > 0.f ? acc.w : __expf(acc.w) - 1.f;
    ((float4*)X1A_D)[w * 32 + lane] = acc;
}

// -------------------- fused softmax + aggregation, layer 1 -------------------
__global__ void gat1_fused_kernel() {
    int w = (blockIdx.x * blockDim.x + threadIdx.x) >> 5;
    int lane = threadIdx.x & 31;
    if (w >= NN) return;
    int s0 = ROWPTR_D[w], s1 = ROWPTR_D[w + 1];

    float edv[HH];
#pragma unroll
    for (int h = 0; h < HH; h++) edv[h] = ED_D[w * HH + h];

    float m[HH];
#pragma unroll
    for (int h = 0; h < HH; h++) m[h] = -1e30f;
    for (int p = s0 + lane; p < s1; p += 32) {
        int s = SRCP_D[p];
        float4 e03 = ((const float4*)ES_D)[s * 2];
        float4 e47 = ((const float4*)ES_D)[s * 2 + 1];
        float ev[HH] = {e03.x, e03.y, e03.z, e03.w, e47.x, e47.y, e47.z, e47.w};
#pragma unroll
        for (int h = 0; h < HH; h++) m[h] = fmaxf(m[h], lrelu(ev[h] + edv[h]));
    }
#pragma unroll
    for (int h = 0; h < HH; h++) m[h] = warp_max(m[h]);

    const float4* X4 = (const float4*)X1A_D;
    float4 acc[HH];
    float zsum[HH];
#pragma unroll
    for (int h = 0; h < HH; h++) { acc[h] = make_float4(0.f, 0.f, 0.f, 0.f); zsum[h] = 0.f; }
    for (int p = s0; p < s1; ++p) {
        int s = SRCP_D[p];
        float4 e03 = ((const float4*)ES_D)[s * 2];
        float4 e47 = ((const float4*)ES_D)[s * 2 + 1];
        float ev[HH] = {e03.x, e03.y, e03.z, e03.w, e47.x, e47.y, e47.z, e47.w};
        float4 v = X4[s * 32 + lane];
#pragma unroll
        for (int h = 0; h < HH; h++) {
            float z = __expf(lrelu(ev[h] + edv[h]) - m[h]);
            acc[h].x += z * v.x;
            acc[h].y += z * v.y;
            acc[h].z += z * v.z;
            acc[h].w += z * v.w;
            zsum[h] += z;
        }
    }
    float4* AG4 = (float4*)AGG_D;
    int base = w * 256;
#pragma unroll
    for (int h = 0; h < HH; h++) {
        float inv = 1.f / fmaxf(zsum[h], 1e-16f);
        float4 o = make_float4(acc[h].x * inv, acc[h].y * inv,
                               acc[h].z * inv, acc[h].w * inv);
        AG4[base + h * 32 + lane] = o;
    }
}

// ----------------------------- GCN aggregation -------------------------------
__global__ void gcn_agg_kernel(const float* __restrict__ Hin, float* __restrict__ Out) {
    int w = (blockIdx.x * blockDim.x + threadIdx.x) >> 5;
    int lane = threadIdx.x & 31;
    if (w >= NN) return;
    int s0 = ROWPTR_D[w], s1 = ROWPTR_D[w + 1];
    float dsum = 0.f;
    for (int p = s0 + lane; p < s1; p += 32) dsum += WP_D[p];
    dsum = warp_sum(dsum);
    float inv = 1.f / fmaxf(dsum, 1e-16f);
    float4 acc = make_float4(0.f, 0.f, 0.f, 0.f);
    const float4* H4 = (const float4*)Hin;
    for (int p = s0; p < s1; ++p) {
        float c = WP_D[p] * inv;
        float4 v = H4[SRCP_D[p] * 32 + lane];
        acc.x += c * v.x; acc.y += c * v.y; acc.z += c * v.z; acc.w += c * v.w;
    }
    acc.x = fmaxf(acc.x, 0.f);
    acc.y = fmaxf(acc.y, 0.f);
    acc.z = fmaxf(acc.z, 0.f);
    acc.w = fmaxf(acc.w, 0.f);
    ((float4*)Out)[w * 32 + lane] = acc;
}

// ----------------------------- launch ----------------------------------------
extern "C" void kernel_launch(void* const* d_in, const int* in_sizes, int n_in,
                              void* d_out, int out_size) {
    const float* x   = (const float*)d_in[0];
    const void*  ei  = d_in[1];   // int64 or int32 [2, E] — auto-detected
    const float* ew  = (const float*)d_in[2];
    const float* W0  = (const float*)d_in[3];
    const float* a0s = (const float*)d_in[4];
    const float* a0d = (const float*)d_in[5];
    const float* W1  = (const float*)d_in[6];
    const float* a1s = (const float*)d_in[7];
    const float* a1d = (const float*)d_in[8];
    const float* G0  = (const float*)d_in[9];
    const float* G1  = (const float*)d_in[10];
    float* out = (float*)d_out;

    float *wh, *agg, *x2a, *x2b;
    cudaGetSymbolAddress((void**)&wh,  WH_D);
    cudaGetSymbolAddress((void**)&agg, AGG_D);
    cudaGetSymbolAddress((void**)&x2a, X2A_D);
    cudaGetSymbolAddress((void**)&x2b, X2B_D);
    __nv_bfloat16 *bt0h, *bt0l, *bt1h, *bt1l, *bg0h, *bg0l, *bg1h, *bg1l;
    cudaGetSymbolAddress((void**)&bt0h, BT0H_D);
    cudaGetSymbolAddress((void**)&bt0l, BT0L_D);
    cudaGetSymbolAddress((void**)&bt1h, BT1H_D);
    cudaGetSymbolAddress((void**)&bt1l, BT1L_D);
    cudaGetSymbolAddress((void**)&bg0h, BG0H_D);
    cudaGetSymbolAddress((void**)&bg0l, BG0L_D);
    cudaGetSymbolAddress((void**)&bg1h, BG1H_D);
    cudaGetSymbolAddress((void**)&bg1l, BG1L_D);

    const int EB   = (EE + 255) / 256;        // 3125
    const int NB   = (NN + 255) / 256;        // 196
    const int NHB  = (NN * HH + 255) / 256;   // 1563
    const int WGB  = (NN * 32 + 255) / 256;   // 6250 (one warp per node)
    const int TCB  = (NN + 63) / 64;          // 782
    const int SCNB = (NN + 1023) / 1024;      // 49

    // CSR build
    zero_kernel<<<NB, 256>>>();
    detect_kernel<<<EB, 256>>>(ei);
    convert_kernel<<<EB, 256>>>(ei);
    scan1_kernel<<<SCNB, 1024>>>();
    scan2_kernel<<<1, 32>>>(SCNB);
    scan3_kernel<<<NB, 256>>>();
    scatter_kernel<<<EB, 256>>>(ew);

    // weight prep (bf16 hi/lo transposed weights + attention bias vectors)
    packBT0_kernel<<<64, 256>>>(W0);
    packBT1_kernel<<<512, 256>>>(W1);
    packBTG_kernel<<<64, 256>>>(G0, bg0h, bg0l);
    packBTG_kernel<<<64, 256>>>(G1, bg1h, bg1l);
    bvec_kernel<<<4, 256>>>(W1, a1s, a1d);

    // GAT layer 0
    mma_gemm<<<TCB, 128>>>(x, bt0h, bt0l, wh, NN, 128, 1.f, nullptr);
    esed0_kernel<<<NHB, 256>>>(a0s, a0d);
    gat0_fused_kernel<<<WGB, 256>>>();

    // GAT layer 1
    esed1_kernel<<<NHB, 256>>>();
    gat1_fused_kernel<<<WGB, 256>>>();

    // GCN branch
    mma_gemm<<<TCB, 128>>>(x, bg0h, bg0l, wh, NN, 128, 1.f, nullptr);
    gcn_agg_kernel<<<WGB, 256>>>(wh, x2a);
    mma_gemm<<<TCB, 128>>>(x2a, bg1h, bg1l, wh, NN, 128, 1.f, nullptr);
    gcn_agg_kernel<<<WGB, 256>>>(wh, x2b);

    // final GAT projection with fused elementwise max(out_gat, X2B)
    mma_gemm<<<TCB, 128>>>(agg, bt1h, bt1l, out, NN, 1024, 0.125f, x2b);
}